// round 5
// baseline (speedup 1.0000x reference)
#include <cuda_runtime.h>
#include <cstdint>

#define IMG    256
#define NPIX   (IMG*IMG)
#define BS     8
#define LEN    64
#define KSEL   5
#define NPAIR  (BS*LEN)
#define CHUNKS 8
#define GP     8                      // pairs per group
#define GROUPS (LEN/GP)               // 8
#define THREADS 256
#define F4_PER_CHUNK (NPIX/4/CHUNKS)  // 2048 float4 per chunk
#define ITERS (F4_PER_CHUNK/THREADS)  // 8

// partial top-5 per (pair, chunk), packed key = (float_bits(d)<<32)|idx
__device__ unsigned long long g_part[NPAIR][CHUNKS][KSEL];

// ---------------------------------------------------------------------------
// Kernel A: fused pooled-gather + chunked top-5.
// CTA = (chunk, group, b). Handles 8 pairs (group*8..group*8+7) of image b
// over pixel chunk [chunk*8192, chunk*8192+8192). Each loaded pixel feeds all
// 8 pairs -> 8x less L2 traffic than pair-per-CTA (R1 was L2-BW bound).
// ---------------------------------------------------------------------------
__global__ void __launch_bounds__(THREADS) topk_kernel(const float* __restrict__ preds,
                                                       const float* __restrict__ ref) {
    const int chunk = blockIdx.x;
    const int group = blockIdx.y;
    const int b     = blockIdx.z;
    const int t = threadIdx.x, lane = t & 31, warp = t >> 5;

    // --- pooled colors for this CTA's 8 pairs ---
    __shared__ float s_p[GP][3];
    if (t < GP) {
        int l = group * GP + t;          // pair = b*64 + l
        int r = l * BS + b;              // flat row in pos_flat
        int sb = r >> 6, sl = r & 63;
        float x = preds[(sb * LEN + sl) * 8 + 0];
        float y = preds[(sb * LEN + sl) * 8 + 1];
        float cx = x * 256.0f - 0.5f;
        float cy = y * 256.0f - 0.5f;
        int ix = (int)rintf(cx);         // round-half-even == jnp.rint
        int iy = (int)rintf(cy);
        float v0 = 0.0f, v1 = 0.0f, v2 = 0.0f;
        if (ix >= 0 && ix < IMG && iy >= 0 && iy < IMG) {
            int off = iy * IMG + ix;
            v0 = ref[(b * 3 + 0) * NPIX + off];
            v1 = ref[(b * 3 + 1) * NPIX + off];
            v2 = ref[(b * 3 + 2) * NPIX + off];
        }
        s_p[t][0] = v0; s_p[t][1] = v1; s_p[t][2] = v2;
    }
    __syncthreads();

    float pc[GP][3];
#pragma unroll
    for (int j = 0; j < GP; j++)
#pragma unroll
        for (int c = 0; c < 3; c++) pc[j][c] = s_p[j][c];

    // per-thread sorted top-5 per pair
    float bd[GP][5];
    int   bi[GP][5];
#pragma unroll
    for (int j = 0; j < GP; j++)
#pragma unroll
        for (int k = 0; k < 5; k++) { bd[j][k] = 3e38f; bi[j][k] = 0; }

    const float4* __restrict__ r0 = (const float4*)(ref + (size_t)(b * 3 + 0) * NPIX);
    const float4* __restrict__ r1 = (const float4*)(ref + (size_t)(b * 3 + 1) * NPIX);
    const float4* __restrict__ r2 = (const float4*)(ref + (size_t)(b * 3 + 2) * NPIX);

#define TRYINSJ(j, dv, iv) do {                                              \
    if ((dv) < bd[j][4]) {                                                   \
        if ((dv) < bd[j][3]) { bd[j][4]=bd[j][3]; bi[j][4]=bi[j][3];         \
            if ((dv) < bd[j][2]) { bd[j][3]=bd[j][2]; bi[j][3]=bi[j][2];     \
                if ((dv) < bd[j][1]) { bd[j][2]=bd[j][1]; bi[j][2]=bi[j][1]; \
                    if ((dv) < bd[j][0]) { bd[j][1]=bd[j][0]; bi[j][1]=bi[j][0]; \
                                           bd[j][0]=(dv); bi[j][0]=(iv); }   \
                    else                 { bd[j][1]=(dv); bi[j][1]=(iv); }   \
                } else { bd[j][2]=(dv); bi[j][2]=(iv); }                     \
            } else { bd[j][3]=(dv); bi[j][3]=(iv); }                         \
        } else { bd[j][4]=(dv); bi[j][4]=(iv); }                             \
    } } while (0)

#pragma unroll
    for (int i = 0; i < ITERS; i++) {
        int gi = chunk * F4_PER_CHUNK + i * THREADS + t;   // coalesced float4
        float4 a = r0[gi];
        float4 e = r1[gi];
        float4 f = r2[gi];
        int base = gi * 4;
#pragma unroll
        for (int j = 0; j < GP; j++) {
            float p0 = pc[j][0], p1 = pc[j][1], p2 = pc[j][2];
            float dx, dy, dz;
            dx = a.x - p0; dy = e.x - p1; dz = f.x - p2;
            float d0 = fmaf(dz, dz, fmaf(dy, dy, dx * dx));
            dx = a.y - p0; dy = e.y - p1; dz = f.y - p2;
            float d1 = fmaf(dz, dz, fmaf(dy, dy, dx * dx));
            dx = a.z - p0; dy = e.z - p1; dz = f.z - p2;
            float d2 = fmaf(dz, dz, fmaf(dy, dy, dx * dx));
            dx = a.w - p0; dy = e.w - p1; dz = f.w - p2;
            float d3 = fmaf(dz, dz, fmaf(dy, dy, dx * dx));

            float m = fminf(fminf(d0, d1), fminf(d2, d3));
            if (m < bd[j][4]) {                    // rare path
                TRYINSJ(j, d0, base + 0);
                TRYINSJ(j, d1, base + 1);
                TRYINSJ(j, d2, base + 2);
                TRYINSJ(j, d3, base + 3);
            }
        }
    }
#undef TRYINSJ

    // ---- reduction: per-warp (all 8 pairs, sequential) then cross-warp ----
    __shared__ unsigned long long buf[8][160];      // 10KB: one warp's 32x5 keys
    __shared__ unsigned long long sw[GP][8][KSEL];  // 2.5KB: warp winners

    for (int j = 0; j < GP; j++) {
#pragma unroll
        for (int k = 0; k < 5; k++)
            buf[warp][lane * 5 + k] =
                ((unsigned long long)__float_as_uint(bd[j][k]) << 32) | (unsigned int)bi[j][k];
        __syncwarp();
#pragma unroll
        for (int k = 0; k < KSEL; k++) {
            unsigned long long m = 0xFFFFFFFFFFFFFFFFull;
#pragma unroll
            for (int i = 0; i < 5; i++) {
                unsigned long long v = buf[warp][i * 32 + lane];
                if (v < m) m = v;
            }
#pragma unroll
            for (int off = 16; off; off >>= 1) {
                unsigned long long o = __shfl_xor_sync(0xffffffffu, m, off);
                if (o < m) m = o;
            }
            if (lane == 0) sw[j][warp][k] = m;
#pragma unroll
            for (int i = 0; i < 5; i++)
                if (buf[warp][i * 32 + lane] == m) buf[warp][i * 32 + lane] = 0xFFFFFFFFFFFFFFFFull;
            __syncwarp();
        }
    }
    __syncthreads();

    if (warp < GP) {   // warp w reduces pair w's 8x5 = 40 warp winners
        const unsigned long long* s = &sw[warp][0][0];     // 40 elems
        unsigned long long v0 = (lane < 40) ? s[lane] : 0xFFFFFFFFFFFFFFFFull;
        unsigned long long v1 = (lane + 32 < 40) ? s[lane + 32] : 0xFFFFFFFFFFFFFFFFull;
        int pair = b * LEN + group * GP + warp;
#pragma unroll
        for (int k = 0; k < KSEL; k++) {
            unsigned long long m = v0 < v1 ? v0 : v1;
#pragma unroll
            for (int off = 16; off; off >>= 1) {
                unsigned long long o = __shfl_xor_sync(0xffffffffu, m, off);
                if (o < m) m = o;
            }
            if (lane == 0) g_part[pair][chunk][k] = m;
            if (v0 == m) v0 = 0xFFFFFFFFFFFFFFFFull;
            if (v1 == m) v1 = 0xFFFFFFFFFFFFFFFFull;
        }
    }
}

// ---------------------------------------------------------------------------
// Kernel B: merge 8 chunk-partials per pair -> global top-5, then roll +
// argmin(first-min ties) + squared error + mean.  One CTA, 512 threads.
// ---------------------------------------------------------------------------
__global__ void __launch_bounds__(512) merge_loss_kernel(const float* __restrict__ preds,
                                                         float* __restrict__ out) {
    int p = threadIdx.x;                 // p = b*64 + l
    int b = p >> 6, l = p & 63;

    unsigned long long b0 = ~0ull, b1 = ~0ull, b2 = ~0ull, b3 = ~0ull, b4 = ~0ull;
#pragma unroll
    for (int c = 0; c < CHUNKS; c++) {
#pragma unroll
        for (int k = 0; k < KSEL; k++) {
            unsigned long long v = g_part[p][c][k];
            if (v < b4) {
                if (v < b3) { b4 = b3;
                    if (v < b2) { b3 = b2;
                        if (v < b1) { b2 = b1;
                            if (v < b0) { b1 = b0; b0 = v; } else b1 = v;
                        } else b2 = v;
                    } else b3 = v;
                } else b4 = v;
            }
        }
    }

    __shared__ unsigned int s_idx[NPAIR][KSEL];
    s_idx[p][0] = (unsigned int)b0;
    s_idx[p][1] = (unsigned int)b1;
    s_idx[p][2] = (unsigned int)b2;
    s_idx[p][3] = (unsigned int)b3;
    s_idx[p][4] = (unsigned int)b4;
    __syncthreads();

    float term = 0.0f;
    if (l >= 1) {
        float px = preds[(b * LEN + l) * 8 + 0];
        float py = preds[(b * LEN + l) * 8 + 1];
        int src = b * LEN + (l - 1);           // tgt_down[b,l] = tgt[b,l-1]
        float bestD = 3e38f, bx = 0.0f, by = 0.0f;
#pragma unroll
        for (int k = 0; k < KSEL; k++) {
            unsigned int idx = s_idx[src][k];
            float tx = (float)(idx & 255u) * (1.0f / 256.0f);
            float ty = (float)(idx >> 8)   * (1.0f / 256.0f);
            float dx = px - tx, dy = py - ty;
            float dd = dx * dx + dy * dy;
            if (dd < bestD) { bestD = dd; bx = tx; by = ty; }  // first min wins
        }
        float ex = px - bx, ey = py - by;
        term = ex * ex + ey * ey;
    }

    __shared__ float s[512];
    s[p] = term;
    __syncthreads();
    for (int st = 256; st; st >>= 1) {
        if (p < st) s[p] += s[p + st];
        __syncthreads();
    }
    if (p == 0) out[0] = s[0] / (float)(BS * (LEN - 1));
}

// ---------------------------------------------------------------------------
extern "C" void kernel_launch(void* const* d_in, const int* in_sizes, int n_in,
                              void* d_out, int out_size) {
    const float* preds = (const float*)d_in[0];   // (8, 64, 8) float32
    const float* ref   = (const float*)d_in[1];   // (8, 3, 256, 256) float32
    float* out = (float*)d_out;

    dim3 grid(CHUNKS, GROUPS, BS);
    topk_kernel<<<grid, THREADS>>>(preds, ref);
    merge_loss_kernel<<<1, 512>>>(preds, out);
}

// round 7
// speedup vs baseline: 3.0292x; 3.0292x over previous
#include <cuda_runtime.h>
#include <cstdint>

#define IMG    256
#define NPIX   (IMG*IMG)
#define BS     8
#define LEN    64
#define KSEL   5
#define NPAIR  (BS*LEN)
#define CHUNKS 8
#define GP     8                      // pairs per group
#define GROUPS (LEN/GP)               // 8
#define THREADS 256
#define F4_PER_CHUNK (NPIX/4/CHUNKS)  // 2048 float4 per chunk
#define ITERS (F4_PER_CHUNK/THREADS)  // 8

// partial top-5 per (pair, chunk), packed key = (float_bits(d)<<32)|idx
__device__ unsigned long long g_part[NPAIR][CHUNKS][KSEL];

// ---------------------------------------------------------------------------
// Kernel A: fused pooled-gather + chunked top-5.
// CTA = (chunk, group, b). Handles 8 pairs (group*8..group*8+7) of image b
// over pixel chunk [chunk*8192, chunk*8192+8192). Each loaded pixel feeds all
// 8 pairs -> 8x less L2 traffic than pair-per-CTA (R1 was L2-BW bound).
// CRITICAL: every access to bd[]/bi[] must use compile-time indices (all
// loops touching them fully unrolled) or ptxas demotes them to local memory
// (this caused R5's 520us regression).
// ---------------------------------------------------------------------------
__global__ void __launch_bounds__(THREADS) topk_kernel(const float* __restrict__ preds,
                                                       const float* __restrict__ ref) {
    const int chunk = blockIdx.x;
    const int group = blockIdx.y;
    const int b     = blockIdx.z;
    const int t = threadIdx.x, lane = t & 31, warp = t >> 5;

    // --- pooled colors for this CTA's 8 pairs ---
    __shared__ float s_p[GP][3];
    if (t < GP) {
        int l = group * GP + t;          // pair = b*64 + l
        int r = l * BS + b;              // flat row in pos_flat
        int sb = r >> 6, sl = r & 63;
        float x = preds[(sb * LEN + sl) * 8 + 0];
        float y = preds[(sb * LEN + sl) * 8 + 1];
        float cx = x * 256.0f - 0.5f;
        float cy = y * 256.0f - 0.5f;
        int ix = (int)rintf(cx);         // round-half-even == jnp.rint
        int iy = (int)rintf(cy);
        float v0 = 0.0f, v1 = 0.0f, v2 = 0.0f;
        if (ix >= 0 && ix < IMG && iy >= 0 && iy < IMG) {
            int off = iy * IMG + ix;
            v0 = ref[(b * 3 + 0) * NPIX + off];
            v1 = ref[(b * 3 + 1) * NPIX + off];
            v2 = ref[(b * 3 + 2) * NPIX + off];
        }
        s_p[t][0] = v0; s_p[t][1] = v1; s_p[t][2] = v2;
    }
    __syncthreads();

    float pc[GP][3];
#pragma unroll
    for (int j = 0; j < GP; j++)
#pragma unroll
        for (int c = 0; c < 3; c++) pc[j][c] = s_p[j][c];

    // per-thread sorted top-5 per pair (MUST stay in registers)
    float bd[GP][5];
    int   bi[GP][5];
#pragma unroll
    for (int j = 0; j < GP; j++)
#pragma unroll
        for (int k = 0; k < 5; k++) { bd[j][k] = 3e38f; bi[j][k] = 0; }

    const float4* __restrict__ r0 = (const float4*)(ref + (size_t)(b * 3 + 0) * NPIX);
    const float4* __restrict__ r1 = (const float4*)(ref + (size_t)(b * 3 + 1) * NPIX);
    const float4* __restrict__ r2 = (const float4*)(ref + (size_t)(b * 3 + 2) * NPIX);

#define TRYINSJ(j, dv, iv) do {                                              \
    if ((dv) < bd[j][4]) {                                                   \
        if ((dv) < bd[j][3]) { bd[j][4]=bd[j][3]; bi[j][4]=bi[j][3];         \
            if ((dv) < bd[j][2]) { bd[j][3]=bd[j][2]; bi[j][3]=bi[j][2];     \
                if ((dv) < bd[j][1]) { bd[j][2]=bd[j][1]; bi[j][2]=bi[j][1]; \
                    if ((dv) < bd[j][0]) { bd[j][1]=bd[j][0]; bi[j][1]=bi[j][0]; \
                                           bd[j][0]=(dv); bi[j][0]=(iv); }   \
                    else                 { bd[j][1]=(dv); bi[j][1]=(iv); }   \
                } else { bd[j][2]=(dv); bi[j][2]=(iv); }                     \
            } else { bd[j][3]=(dv); bi[j][3]=(iv); }                         \
        } else { bd[j][4]=(dv); bi[j][4]=(iv); }                             \
    } } while (0)

#pragma unroll 2
    for (int i = 0; i < ITERS; i++) {
        int gi = chunk * F4_PER_CHUNK + i * THREADS + t;   // coalesced float4
        float4 a = r0[gi];
        float4 e = r1[gi];
        float4 f = r2[gi];
        int base = gi * 4;
#pragma unroll
        for (int j = 0; j < GP; j++) {
            float p0 = pc[j][0], p1 = pc[j][1], p2 = pc[j][2];
            float dx, dy, dz;
            dx = a.x - p0; dy = e.x - p1; dz = f.x - p2;
            float d0 = fmaf(dz, dz, fmaf(dy, dy, dx * dx));
            dx = a.y - p0; dy = e.y - p1; dz = f.y - p2;
            float d1 = fmaf(dz, dz, fmaf(dy, dy, dx * dx));
            dx = a.z - p0; dy = e.z - p1; dz = f.z - p2;
            float d2 = fmaf(dz, dz, fmaf(dy, dy, dx * dx));
            dx = a.w - p0; dy = e.w - p1; dz = f.w - p2;
            float d3 = fmaf(dz, dz, fmaf(dy, dy, dx * dx));

            float m = fminf(fminf(d0, d1), fminf(d2, d3));
            if (m < bd[j][4]) {                    // rare path
                TRYINSJ(j, d0, base + 0);
                TRYINSJ(j, d1, base + 1);
                TRYINSJ(j, d2, base + 2);
                TRYINSJ(j, d3, base + 3);
            }
        }
    }
#undef TRYINSJ

    // ---- reduction: per-warp (all 8 pairs, sequential) then cross-warp ----
    __shared__ unsigned long long buf[8][160];      // 10KB: one warp's 32x5 keys
    __shared__ unsigned long long sw[GP][8][KSEL];  // 2.5KB: warp winners

#pragma unroll      // <-- critical: keeps bd/bi register-resident
    for (int j = 0; j < GP; j++) {
#pragma unroll
        for (int k = 0; k < 5; k++)
            buf[warp][lane * 5 + k] =
                ((unsigned long long)__float_as_uint(bd[j][k]) << 32) | (unsigned int)bi[j][k];
        __syncwarp();
#pragma unroll
        for (int k = 0; k < KSEL; k++) {
            unsigned long long m = 0xFFFFFFFFFFFFFFFFull;
#pragma unroll
            for (int i = 0; i < 5; i++) {
                unsigned long long v = buf[warp][i * 32 + lane];
                if (v < m) m = v;
            }
#pragma unroll
            for (int off = 16; off; off >>= 1) {
                unsigned long long o = __shfl_xor_sync(0xffffffffu, m, off);
                if (o < m) m = o;
            }
            if (lane == 0) sw[j][warp][k] = m;
#pragma unroll
            for (int i = 0; i < 5; i++)
                if (buf[warp][i * 32 + lane] == m) buf[warp][i * 32 + lane] = 0xFFFFFFFFFFFFFFFFull;
            __syncwarp();
        }
    }
    __syncthreads();

    if (warp < GP) {   // warp w reduces pair w's 8x5 = 40 warp winners
        const unsigned long long* s = &sw[warp][0][0];     // 40 elems
        unsigned long long v0 = (lane < 40) ? s[lane] : 0xFFFFFFFFFFFFFFFFull;
        unsigned long long v1 = (lane + 32 < 40) ? s[lane + 32] : 0xFFFFFFFFFFFFFFFFull;
        int pair = b * LEN + group * GP + warp;
#pragma unroll
        for (int k = 0; k < KSEL; k++) {
            unsigned long long m = v0 < v1 ? v0 : v1;
#pragma unroll
            for (int off = 16; off; off >>= 1) {
                unsigned long long o = __shfl_xor_sync(0xffffffffu, m, off);
                if (o < m) m = o;
            }
            if (lane == 0) g_part[pair][chunk][k] = m;
            if (v0 == m) v0 = 0xFFFFFFFFFFFFFFFFull;
            if (v1 == m) v1 = 0xFFFFFFFFFFFFFFFFull;
        }
    }
}

// ---------------------------------------------------------------------------
// Kernel B: merge 8 chunk-partials per pair -> global top-5, then roll +
// argmin(first-min ties) + squared error + mean.  One CTA, 512 threads.
// ---------------------------------------------------------------------------
__global__ void __launch_bounds__(512) merge_loss_kernel(const float* __restrict__ preds,
                                                         float* __restrict__ out) {
    int p = threadIdx.x;                 // p = b*64 + l
    int b = p >> 6, l = p & 63;

    unsigned long long b0 = ~0ull, b1 = ~0ull, b2 = ~0ull, b3 = ~0ull, b4 = ~0ull;
#pragma unroll
    for (int c = 0; c < CHUNKS; c++) {
#pragma unroll
        for (int k = 0; k < KSEL; k++) {
            unsigned long long v = g_part[p][c][k];
            if (v < b4) {
                if (v < b3) { b4 = b3;
                    if (v < b2) { b3 = b2;
                        if (v < b1) { b2 = b1;
                            if (v < b0) { b1 = b0; b0 = v; } else b1 = v;
                        } else b2 = v;
                    } else b3 = v;
                } else b4 = v;
            }
        }
    }

    __shared__ unsigned int s_idx[NPAIR][KSEL];
    s_idx[p][0] = (unsigned int)b0;
    s_idx[p][1] = (unsigned int)b1;
    s_idx[p][2] = (unsigned int)b2;
    s_idx[p][3] = (unsigned int)b3;
    s_idx[p][4] = (unsigned int)b4;
    __syncthreads();

    float term = 0.0f;
    if (l >= 1) {
        float px = preds[(b * LEN + l) * 8 + 0];
        float py = preds[(b * LEN + l) * 8 + 1];
        int src = b * LEN + (l - 1);           // tgt_down[b,l] = tgt[b,l-1]
        float bestD = 3e38f, bx = 0.0f, by = 0.0f;
#pragma unroll
        for (int k = 0; k < KSEL; k++) {
            unsigned int idx = s_idx[src][k];
            float tx = (float)(idx & 255u) * (1.0f / 256.0f);
            float ty = (float)(idx >> 8)   * (1.0f / 256.0f);
            float dx = px - tx, dy = py - ty;
            float dd = dx * dx + dy * dy;
            if (dd < bestD) { bestD = dd; bx = tx; by = ty; }  // first min wins
        }
        float ex = px - bx, ey = py - by;
        term = ex * ex + ey * ey;
    }

    __shared__ float s[512];
    s[p] = term;
    __syncthreads();
    for (int st = 256; st; st >>= 1) {
        if (p < st) s[p] += s[p + st];
        __syncthreads();
    }
    if (p == 0) out[0] = s[0] / (float)(BS * (LEN - 1));
}

// ---------------------------------------------------------------------------
extern "C" void kernel_launch(void* const* d_in, const int* in_sizes, int n_in,
                              void* d_out, int out_size) {
    const float* preds = (const float*)d_in[0];   // (8, 64, 8) float32
    const float* ref   = (const float*)d_in[1];   // (8, 3, 256, 256) float32
    float* out = (float*)d_out;

    dim3 grid(CHUNKS, GROUPS, BS);
    topk_kernel<<<grid, THREADS>>>(preds, ref);
    merge_loss_kernel<<<1, 512>>>(preds, out);
}

// round 9
// speedup vs baseline: 4.0034x; 1.3216x over previous
#include <cuda_runtime.h>
#include <cstdint>

#define IMG    256
#define NPIX   (IMG*IMG)
#define BS     8
#define LEN    64
#define KSEL   5
#define NPAIR  (BS*LEN)
#define CHUNKS 8
#define GP     8                      // pairs per group
#define GROUPS (LEN/GP)               // 8
#define THREADS 256
#define F4_PER_CHUNK (NPIX/4/CHUNKS)  // 2048 float4 per chunk
#define ITERS (F4_PER_CHUNK/THREADS)  // 8
#define CAP    96                     // candidate buffer per pair per CTA
#define NCTAS  (CHUNKS*GROUPS*BS)     // 512

// partial top-5 per (pair, chunk), packed key = (float_bits(d)<<32)|idx
__device__ unsigned long long g_part[NPAIR][CHUNKS][KSEL];
__device__ int g_done;                // zero-init; reset by last CTA each launch

// ---------------------------------------------------------------------------
// Single fused kernel. CTA = (chunk, group, b): 8 pairs of image b over an
// 8192-pixel chunk.
//   Pass 1 (branchless): per-thread min distance per pair -> per-pair
//     threshold T = min over warps of (5th-smallest thread-min in warp).
//     T >= chunk's 5th-smallest distance by construction.
//   Pass 2: recompute d (bit-identical), push d <= T candidates (rare) to a
//     shared buffer, warp-per-pair exact top-5 select -> g_part.
//   Last CTA (fence + counter): merge chunks + roll/argmin/loss -> out.
// ---------------------------------------------------------------------------
__global__ void __launch_bounds__(THREADS) cc_kernel(const float* __restrict__ preds,
                                                     const float* __restrict__ ref,
                                                     float* __restrict__ out) {
    const int chunk = blockIdx.x;
    const int group = blockIdx.y;
    const int b     = blockIdx.z;
    const int t = threadIdx.x, lane = t & 31, warp = t >> 5;

    // --- pooled colors for this CTA's 8 pairs ---
    __shared__ float s_p[GP][3];
    if (t < GP) {
        int l = group * GP + t;          // pair = b*64 + l
        int r = l * BS + b;              // flat row in pos_flat
        int sb = r >> 6, sl = r & 63;
        float x = preds[(sb * LEN + sl) * 8 + 0];
        float y = preds[(sb * LEN + sl) * 8 + 1];
        float cx = x * 256.0f - 0.5f;
        float cy = y * 256.0f - 0.5f;
        int ix = (int)rintf(cx);         // round-half-even == jnp.rint
        int iy = (int)rintf(cy);
        float v0 = 0.0f, v1 = 0.0f, v2 = 0.0f;
        if (ix >= 0 && ix < IMG && iy >= 0 && iy < IMG) {
            int off = iy * IMG + ix;
            v0 = ref[(b * 3 + 0) * NPIX + off];
            v1 = ref[(b * 3 + 1) * NPIX + off];
            v2 = ref[(b * 3 + 2) * NPIX + off];
        }
        s_p[t][0] = v0; s_p[t][1] = v1; s_p[t][2] = v2;
    }
    __syncthreads();

    float pc[GP][3];
#pragma unroll
    for (int j = 0; j < GP; j++)
#pragma unroll
        for (int c = 0; c < 3; c++) pc[j][c] = s_p[j][c];

    const float4* __restrict__ r0 = (const float4*)(ref + (size_t)(b * 3 + 0) * NPIX);
    const float4* __restrict__ r1 = (const float4*)(ref + (size_t)(b * 3 + 1) * NPIX);
    const float4* __restrict__ r2 = (const float4*)(ref + (size_t)(b * 3 + 2) * NPIX);

    // ================= PASS 1: branchless per-thread min per pair ==========
    float mn[GP];
#pragma unroll
    for (int j = 0; j < GP; j++) mn[j] = 3e38f;

#pragma unroll
    for (int i = 0; i < ITERS; i++) {
        int gi = chunk * F4_PER_CHUNK + i * THREADS + t;   // coalesced float4
        float4 a = r0[gi];
        float4 e = r1[gi];
        float4 f = r2[gi];
#pragma unroll
        for (int j = 0; j < GP; j++) {
            float p0 = pc[j][0], p1 = pc[j][1], p2 = pc[j][2];
            float dx, dy, dz;
            dx = a.x - p0; dy = e.x - p1; dz = f.x - p2;
            float d0 = fmaf(dz, dz, fmaf(dy, dy, dx * dx));
            dx = a.y - p0; dy = e.y - p1; dz = f.y - p2;
            float d1 = fmaf(dz, dz, fmaf(dy, dy, dx * dx));
            dx = a.z - p0; dy = e.z - p1; dz = f.z - p2;
            float d2 = fmaf(dz, dz, fmaf(dy, dy, dx * dx));
            dx = a.w - p0; dy = e.w - p1; dz = f.w - p2;
            float d3 = fmaf(dz, dz, fmaf(dy, dy, dx * dx));
            mn[j] = fminf(mn[j], fminf(fminf(d0, d1), fminf(d2, d3)));
        }
    }

    // Per pair: warp 5th-smallest-with-removal, then min over warps.
    __shared__ float sT[GP][8];
#pragma unroll
    for (int j = 0; j < GP; j++) {
        float m = mn[j];
        float fifth = 3e38f;
#pragma unroll
        for (int k = 0; k < KSEL; k++) {
            float w = m;
#pragma unroll
            for (int off = 16; off; off >>= 1) w = fminf(w, __shfl_xor_sync(0xffffffffu, w, off));
            if (m == w) m = 3e38f;       // remove (ties all removed -> T only grows: safe)
            fifth = w;
        }
        if (lane == 0) sT[j][warp] = fifth;
    }
    __syncthreads();

    float Tj[GP];
#pragma unroll
    for (int j = 0; j < GP; j++) {
        float x = sT[j][0];
#pragma unroll
        for (int w = 1; w < 8; w++) x = fminf(x, sT[j][w]);
        Tj[j] = x;                        // >= chunk's 5th-smallest distance
    }

    // ================= PASS 2: collect candidates d <= T ===================
    __shared__ unsigned long long cand[GP][CAP];
    __shared__ int cnt[GP];
    if (t < GP) cnt[t] = 0;
    __syncthreads();

#pragma unroll
    for (int i = 0; i < ITERS; i++) {
        int gi = chunk * F4_PER_CHUNK + i * THREADS + t;
        float4 a = r0[gi];
        float4 e = r1[gi];
        float4 f = r2[gi];
        int base = gi * 4;
#pragma unroll
        for (int j = 0; j < GP; j++) {
            float p0 = pc[j][0], p1 = pc[j][1], p2 = pc[j][2];
            float dx, dy, dz;
            dx = a.x - p0; dy = e.x - p1; dz = f.x - p2;
            float d0 = fmaf(dz, dz, fmaf(dy, dy, dx * dx));
            dx = a.y - p0; dy = e.y - p1; dz = f.y - p2;
            float d1 = fmaf(dz, dz, fmaf(dy, dy, dx * dx));
            dx = a.z - p0; dy = e.z - p1; dz = f.z - p2;
            float d2 = fmaf(dz, dz, fmaf(dy, dy, dx * dx));
            dx = a.w - p0; dy = e.w - p1; dz = f.w - p2;
            float d3 = fmaf(dz, dz, fmaf(dy, dy, dx * dx));
            float m = fminf(fminf(d0, d1), fminf(d2, d3));
            float T = Tj[j];
            if (m <= T) {                 // rare: expected ~tens per pair-chunk warp-wide
                if (d0 <= T) { int s = atomicAdd(&cnt[j], 1);
                    if (s < CAP) cand[j][s] = ((unsigned long long)__float_as_uint(d0) << 32) | (unsigned int)(base + 0); }
                if (d1 <= T) { int s = atomicAdd(&cnt[j], 1);
                    if (s < CAP) cand[j][s] = ((unsigned long long)__float_as_uint(d1) << 32) | (unsigned int)(base + 1); }
                if (d2 <= T) { int s = atomicAdd(&cnt[j], 1);
                    if (s < CAP) cand[j][s] = ((unsigned long long)__float_as_uint(d2) << 32) | (unsigned int)(base + 2); }
                if (d3 <= T) { int s = atomicAdd(&cnt[j], 1);
                    if (s < CAP) cand[j][s] = ((unsigned long long)__float_as_uint(d3) << 32) | (unsigned int)(base + 3); }
            }
        }
    }
    __syncthreads();

    // Warp j selects exact top-5 of pair j's candidates (keys unique: idx).
    {
        int j = warp;
        int n = cnt[j] < CAP ? cnt[j] : CAP;   // n >= 5 guaranteed by T
        unsigned long long v0 = (lane      < n) ? cand[j][lane]      : 0xFFFFFFFFFFFFFFFFull;
        unsigned long long v1 = (lane + 32 < n) ? cand[j][lane + 32] : 0xFFFFFFFFFFFFFFFFull;
        unsigned long long v2 = (lane + 64 < n) ? cand[j][lane + 64] : 0xFFFFFFFFFFFFFFFFull;
        int pair = b * LEN + group * GP + j;
#pragma unroll
        for (int k = 0; k < KSEL; k++) {
            unsigned long long m = v0 < v1 ? v0 : v1;
            if (v2 < m) m = v2;
#pragma unroll
            for (int off = 16; off; off >>= 1) {
                unsigned long long o = __shfl_xor_sync(0xffffffffu, m, off);
                if (o < m) m = o;
            }
            if (lane == 0) g_part[pair][chunk][k] = m;
            if (v0 == m) v0 = 0xFFFFFFFFFFFFFFFFull;
            if (v1 == m) v1 = 0xFFFFFFFFFFFFFFFFull;
            if (v2 == m) v2 = 0xFFFFFFFFFFFFFFFFull;
        }
    }
    __threadfence();                      // release g_part (all threads) before counter
    __syncthreads();

    // ================= last CTA: merge + loss ==============================
    __shared__ int isLast;
    if (t == 0) {
        int prev = atomicAdd(&g_done, 1);
        isLast = (prev == NCTAS - 1);
    }
    __syncthreads();
    if (!isLast) return;
    if (t == 0) g_done = 0;               // reset for next graph replay
    __threadfence();

    __shared__ unsigned int s_idx[NPAIR][KSEL];
#pragma unroll
    for (int rep = 0; rep < 2; rep++) {
        int p = t + rep * 256;
        unsigned long long b0 = ~0ull, b1 = ~0ull, b2 = ~0ull, b3 = ~0ull, b4 = ~0ull;
#pragma unroll
        for (int c = 0; c < CHUNKS; c++) {
#pragma unroll
            for (int k = 0; k < KSEL; k++) {
                unsigned long long v = g_part[p][c][k];
                if (v < b4) {
                    if (v < b3) { b4 = b3;
                        if (v < b2) { b3 = b2;
                            if (v < b1) { b2 = b1;
                                if (v < b0) { b1 = b0; b0 = v; } else b1 = v;
                            } else b2 = v;
                        } else b3 = v;
                    } else b4 = v;
                }
            }
        }
        s_idx[p][0] = (unsigned int)b0;
        s_idx[p][1] = (unsigned int)b1;
        s_idx[p][2] = (unsigned int)b2;
        s_idx[p][3] = (unsigned int)b3;
        s_idx[p][4] = (unsigned int)b4;
    }
    __syncthreads();

    float acc = 0.0f;
#pragma unroll
    for (int rep = 0; rep < 2; rep++) {
        int p = t + rep * 256;
        int pb = p >> 6, pl = p & 63;
        if (pl >= 1) {
            float px = preds[(pb * LEN + pl) * 8 + 0];
            float py = preds[(pb * LEN + pl) * 8 + 1];
            int src = pb * LEN + (pl - 1);        // tgt_down[b,l] = tgt[b,l-1]
            float bestD = 3e38f, bx = 0.0f, by = 0.0f;
#pragma unroll
            for (int k = 0; k < KSEL; k++) {
                unsigned int idx = s_idx[src][k];
                float tx = (float)(idx & 255u) * (1.0f / 256.0f);
                float ty = (float)(idx >> 8)   * (1.0f / 256.0f);
                float ddx = px - tx, ddy = py - ty;
                float dd = ddx * ddx + ddy * ddy;
                if (dd < bestD) { bestD = dd; bx = tx; by = ty; }  // first min wins
            }
            float ex = px - bx, ey = py - by;
            acc += ex * ex + ey * ey;
        }
    }

    __shared__ float s[256];
    s[t] = acc;
    __syncthreads();
    for (int st = 128; st; st >>= 1) {
        if (t < st) s[t] += s[t + st];
        __syncthreads();
    }
    if (t == 0) out[0] = s[0] / (float)(BS * (LEN - 1));
}

// ---------------------------------------------------------------------------
extern "C" void kernel_launch(void* const* d_in, const int* in_sizes, int n_in,
                              void* d_out, int out_size) {
    const float* preds = (const float*)d_in[0];   // (8, 64, 8) float32
    const float* ref   = (const float*)d_in[1];   // (8, 3, 256, 256) float32
    float* out = (float*)d_out;

    dim3 grid(CHUNKS, GROUPS, BS);
    cc_kernel<<<grid, THREADS>>>(preds, ref, out);
}

// round 10
// speedup vs baseline: 9.5915x; 2.3959x over previous
#include <cuda_runtime.h>
#include <cstdint>

#define IMG    256
#define NPIX   (IMG*IMG)
#define BS     8
#define LEN    64
#define KSEL   5
#define NPAIR  (BS*LEN)
#define CHUNKS 8
#define GP     4                      // pairs per CTA (halved: register pressure)
#define GROUPS (LEN/GP)               // 16
#define THREADS 256
#define F4_PER_CHUNK (NPIX/4/CHUNKS)  // 2048 float4 per chunk
#define ITERS (F4_PER_CHUNK/THREADS)  // 8
#define CAP    96                     // candidate buffer per pair per CTA
#define NCTAS  (CHUNKS*GROUPS*BS)     // 1024

// partial top-5 per (pair, chunk), packed key = (float_bits(d)<<32)|idx
__device__ unsigned long long g_part[NPAIR][CHUNKS][KSEL];
__device__ int g_done;                // zero-init; reset by last CTA each launch

// ---------------------------------------------------------------------------
// Single fused kernel. CTA = (chunk, group, b): 4 pairs of image b over an
// 8192-pixel chunk.
//   Pass 1 (branchless): per-thread min distance per pair -> per-pair
//     threshold T = min over warps of (5th-smallest thread-min in warp).
//     T >= chunk's 5th-smallest distance by construction.
//   Pass 2: recompute d (bit-identical), push d <= T candidates (rare) to a
//     shared buffer, warp-per-pair exact top-5 select -> g_part.
//   Last CTA (fence + counter): merge chunks + roll/argmin/loss -> out.
// Register budget is the binding constraint (R9: 255 regs -> spills + 1
// CTA/SM). GP=4 + unroll 2 + launch_bounds(256,3) targets <=84 regs.
// ---------------------------------------------------------------------------
__global__ void __launch_bounds__(THREADS, 3) cc_kernel(const float* __restrict__ preds,
                                                        const float* __restrict__ ref,
                                                        float* __restrict__ out) {
    const int chunk = blockIdx.x;
    const int group = blockIdx.y;
    const int b     = blockIdx.z;
    const int t = threadIdx.x, lane = t & 31, warp = t >> 5;

    // --- pooled colors for this CTA's 4 pairs ---
    __shared__ float s_p[GP][3];
    if (t < GP) {
        int l = group * GP + t;          // pair = b*64 + l
        int r = l * BS + b;              // flat row in pos_flat
        int sb = r >> 6, sl = r & 63;
        float x = preds[(sb * LEN + sl) * 8 + 0];
        float y = preds[(sb * LEN + sl) * 8 + 1];
        float cx = x * 256.0f - 0.5f;
        float cy = y * 256.0f - 0.5f;
        int ix = (int)rintf(cx);         // round-half-even == jnp.rint
        int iy = (int)rintf(cy);
        float v0 = 0.0f, v1 = 0.0f, v2 = 0.0f;
        if (ix >= 0 && ix < IMG && iy >= 0 && iy < IMG) {
            int off = iy * IMG + ix;
            v0 = ref[(b * 3 + 0) * NPIX + off];
            v1 = ref[(b * 3 + 1) * NPIX + off];
            v2 = ref[(b * 3 + 2) * NPIX + off];
        }
        s_p[t][0] = v0; s_p[t][1] = v1; s_p[t][2] = v2;
    }
    __syncthreads();

    float pc[GP][3];
#pragma unroll
    for (int j = 0; j < GP; j++)
#pragma unroll
        for (int c = 0; c < 3; c++) pc[j][c] = s_p[j][c];

    const float4* __restrict__ r0 = (const float4*)(ref + (size_t)(b * 3 + 0) * NPIX);
    const float4* __restrict__ r1 = (const float4*)(ref + (size_t)(b * 3 + 1) * NPIX);
    const float4* __restrict__ r2 = (const float4*)(ref + (size_t)(b * 3 + 2) * NPIX);

    // ================= PASS 1: branchless per-thread min per pair ==========
    float mn[GP];
#pragma unroll
    for (int j = 0; j < GP; j++) mn[j] = 3e38f;

#pragma unroll 2
    for (int i = 0; i < ITERS; i++) {
        int gi = chunk * F4_PER_CHUNK + i * THREADS + t;   // coalesced float4
        float4 a = r0[gi];
        float4 e = r1[gi];
        float4 f = r2[gi];
#pragma unroll
        for (int j = 0; j < GP; j++) {
            float p0 = pc[j][0], p1 = pc[j][1], p2 = pc[j][2];
            float dx, dy, dz;
            dx = a.x - p0; dy = e.x - p1; dz = f.x - p2;
            float d0 = fmaf(dz, dz, fmaf(dy, dy, dx * dx));
            dx = a.y - p0; dy = e.y - p1; dz = f.y - p2;
            float d1 = fmaf(dz, dz, fmaf(dy, dy, dx * dx));
            dx = a.z - p0; dy = e.z - p1; dz = f.z - p2;
            float d2 = fmaf(dz, dz, fmaf(dy, dy, dx * dx));
            dx = a.w - p0; dy = e.w - p1; dz = f.w - p2;
            float d3 = fmaf(dz, dz, fmaf(dy, dy, dx * dx));
            mn[j] = fminf(mn[j], fminf(fminf(d0, d1), fminf(d2, d3)));
        }
    }

    // Per pair: warp 5th-smallest-with-removal, then min over warps.
    __shared__ float sT[GP][8];
#pragma unroll
    for (int j = 0; j < GP; j++) {
        float m = mn[j];
        float fifth = 3e38f;
#pragma unroll
        for (int k = 0; k < KSEL; k++) {
            float w = m;
#pragma unroll
            for (int off = 16; off; off >>= 1) w = fminf(w, __shfl_xor_sync(0xffffffffu, w, off));
            if (m == w) m = 3e38f;       // remove (ties all removed -> T only grows: safe)
            fifth = w;
        }
        if (lane == 0) sT[j][warp] = fifth;
    }
    __syncthreads();

    float Tj[GP];
#pragma unroll
    for (int j = 0; j < GP; j++) {
        float x = sT[j][0];
#pragma unroll
        for (int w = 1; w < 8; w++) x = fminf(x, sT[j][w]);
        Tj[j] = x;                        // >= chunk's 5th-smallest distance
    }

    // ================= PASS 2: collect candidates d <= T ===================
    __shared__ unsigned long long cand[GP][CAP];
    __shared__ int cnt[GP];
    if (t < GP) cnt[t] = 0;
    __syncthreads();

#pragma unroll 2
    for (int i = 0; i < ITERS; i++) {
        int gi = chunk * F4_PER_CHUNK + i * THREADS + t;
        float4 a = r0[gi];
        float4 e = r1[gi];
        float4 f = r2[gi];
        int base = gi * 4;
#pragma unroll
        for (int j = 0; j < GP; j++) {
            float p0 = pc[j][0], p1 = pc[j][1], p2 = pc[j][2];
            float dx, dy, dz;
            dx = a.x - p0; dy = e.x - p1; dz = f.x - p2;
            float d0 = fmaf(dz, dz, fmaf(dy, dy, dx * dx));
            dx = a.y - p0; dy = e.y - p1; dz = f.y - p2;
            float d1 = fmaf(dz, dz, fmaf(dy, dy, dx * dx));
            dx = a.z - p0; dy = e.z - p1; dz = f.z - p2;
            float d2 = fmaf(dz, dz, fmaf(dy, dy, dx * dx));
            dx = a.w - p0; dy = e.w - p1; dz = f.w - p2;
            float d3 = fmaf(dz, dz, fmaf(dy, dy, dx * dx));
            float m = fminf(fminf(d0, d1), fminf(d2, d3));
            float T = Tj[j];
            if (m <= T) {                 // rare path
                if (d0 <= T) { int s = atomicAdd(&cnt[j], 1);
                    if (s < CAP) cand[j][s] = ((unsigned long long)__float_as_uint(d0) << 32) | (unsigned int)(base + 0); }
                if (d1 <= T) { int s = atomicAdd(&cnt[j], 1);
                    if (s < CAP) cand[j][s] = ((unsigned long long)__float_as_uint(d1) << 32) | (unsigned int)(base + 1); }
                if (d2 <= T) { int s = atomicAdd(&cnt[j], 1);
                    if (s < CAP) cand[j][s] = ((unsigned long long)__float_as_uint(d2) << 32) | (unsigned int)(base + 2); }
                if (d3 <= T) { int s = atomicAdd(&cnt[j], 1);
                    if (s < CAP) cand[j][s] = ((unsigned long long)__float_as_uint(d3) << 32) | (unsigned int)(base + 3); }
            }
        }
    }
    __syncthreads();

    // Warps 0..3: warp j selects exact top-5 of pair j's candidates.
    if (warp < GP) {
        int j = warp;
        int n = cnt[j] < CAP ? cnt[j] : CAP;   // n >= 5 guaranteed by T
        unsigned long long v0 = (lane      < n) ? cand[j][lane]      : 0xFFFFFFFFFFFFFFFFull;
        unsigned long long v1 = (lane + 32 < n) ? cand[j][lane + 32] : 0xFFFFFFFFFFFFFFFFull;
        unsigned long long v2 = (lane + 64 < n) ? cand[j][lane + 64] : 0xFFFFFFFFFFFFFFFFull;
        int pair = b * LEN + group * GP + j;
#pragma unroll
        for (int k = 0; k < KSEL; k++) {
            unsigned long long m = v0 < v1 ? v0 : v1;
            if (v2 < m) m = v2;
#pragma unroll
            for (int off = 16; off; off >>= 1) {
                unsigned long long o = __shfl_xor_sync(0xffffffffu, m, off);
                if (o < m) m = o;
            }
            if (lane == 0) g_part[pair][chunk][k] = m;
            if (v0 == m) v0 = 0xFFFFFFFFFFFFFFFFull;
            if (v1 == m) v1 = 0xFFFFFFFFFFFFFFFFull;
            if (v2 == m) v2 = 0xFFFFFFFFFFFFFFFFull;
        }
    }
    __threadfence();                      // release g_part before counter
    __syncthreads();

    // ================= last CTA: merge + loss ==============================
    __shared__ int isLast;
    if (t == 0) {
        int prev = atomicAdd(&g_done, 1);
        isLast = (prev == NCTAS - 1);
    }
    __syncthreads();
    if (!isLast) return;
    if (t == 0) g_done = 0;               // reset for next graph replay
    __threadfence();

    __shared__ unsigned int s_idx[NPAIR][KSEL];
#pragma unroll
    for (int rep = 0; rep < 2; rep++) {
        int p = t + rep * 256;
        unsigned long long b0 = ~0ull, b1 = ~0ull, b2 = ~0ull, b3 = ~0ull, b4 = ~0ull;
#pragma unroll
        for (int c = 0; c < CHUNKS; c++) {
#pragma unroll
            for (int k = 0; k < KSEL; k++) {
                unsigned long long v = g_part[p][c][k];
                if (v < b4) {
                    if (v < b3) { b4 = b3;
                        if (v < b2) { b3 = b2;
                            if (v < b1) { b2 = b1;
                                if (v < b0) { b1 = b0; b0 = v; } else b1 = v;
                            } else b2 = v;
                        } else b3 = v;
                    } else b4 = v;
                }
            }
        }
        s_idx[p][0] = (unsigned int)b0;
        s_idx[p][1] = (unsigned int)b1;
        s_idx[p][2] = (unsigned int)b2;
        s_idx[p][3] = (unsigned int)b3;
        s_idx[p][4] = (unsigned int)b4;
    }
    __syncthreads();

    float acc = 0.0f;
#pragma unroll
    for (int rep = 0; rep < 2; rep++) {
        int p = t + rep * 256;
        int pb = p >> 6, pl = p & 63;
        if (pl >= 1) {
            float px = preds[(pb * LEN + pl) * 8 + 0];
            float py = preds[(pb * LEN + pl) * 8 + 1];
            int src = pb * LEN + (pl - 1);        // tgt_down[b,l] = tgt[b,l-1]
            float bestD = 3e38f, bx = 0.0f, by = 0.0f;
#pragma unroll
            for (int k = 0; k < KSEL; k++) {
                unsigned int idx = s_idx[src][k];
                float tx = (float)(idx & 255u) * (1.0f / 256.0f);
                float ty = (float)(idx >> 8)   * (1.0f / 256.0f);
                float ddx = px - tx, ddy = py - ty;
                float dd = ddx * ddx + ddy * ddy;
                if (dd < bestD) { bestD = dd; bx = tx; by = ty; }  // first min wins
            }
            float ex = px - bx, ey = py - by;
            acc += ex * ex + ey * ey;
        }
    }

    __shared__ float s[256];
    s[t] = acc;
    __syncthreads();
    for (int st = 128; st; st >>= 1) {
        if (t < st) s[t] += s[t + st];
        __syncthreads();
    }
    if (t == 0) out[0] = s[0] / (float)(BS * (LEN - 1));
}

// ---------------------------------------------------------------------------
extern "C" void kernel_launch(void* const* d_in, const int* in_sizes, int n_in,
                              void* d_out, int out_size) {
    const float* preds = (const float*)d_in[0];   // (8, 64, 8) float32
    const float* ref   = (const float*)d_in[1];   // (8, 3, 256, 256) float32
    float* out = (float*)d_out;

    dim3 grid(CHUNKS, GROUPS, BS);
    cc_kernel<<<grid, THREADS>>>(preds, ref, out);
}

// round 11
// speedup vs baseline: 10.4357x; 1.0880x over previous
#include <cuda_runtime.h>
#include <cstdint>

#define IMG    256
#define NPIX   (IMG*IMG)
#define BS     8
#define LEN    64
#define KSEL   5
#define NPAIR  (BS*LEN)
#define CHUNKS 8
#define GP     4                      // pairs per CTA
#define GROUPS (LEN/GP)               // 16
#define THREADS 256
#define F4_PER_CHUNK (NPIX/4/CHUNKS)  // 2048 float4 per chunk
#define ITERS (F4_PER_CHUNK/THREADS)  // 8
#define CAP    96                     // candidate buffer per pair per CTA
#define NCTAS  (CHUNKS*GROUPS*BS)     // 1024

// partial top-5 per (pair, chunk), packed key = (float_bits(d)<<32)|idx
__device__ unsigned long long g_part[NPAIR][CHUNKS][KSEL];
__device__ int g_done;                // zero-init; reset by last CTA each launch

// ---------------- packed f32x2 helpers (bitwise identical to 2x scalar) ----
__device__ __forceinline__ unsigned long long pk2(float lo, float hi) {
    unsigned long long r;
    asm("mov.b64 %0,{%1,%2};" : "=l"(r) : "f"(lo), "f"(hi));
    return r;
}
__device__ __forceinline__ void upk2(unsigned long long v, float& lo, float& hi) {
    asm("mov.b64 {%0,%1},%2;" : "=f"(lo), "=f"(hi) : "l"(v));
}
__device__ __forceinline__ unsigned long long add2(unsigned long long a, unsigned long long b) {
    unsigned long long r;
    asm("add.rn.f32x2 %0,%1,%2;" : "=l"(r) : "l"(a), "l"(b));
    return r;
}
__device__ __forceinline__ unsigned long long mul2(unsigned long long a, unsigned long long b) {
    unsigned long long r;
    asm("mul.rn.f32x2 %0,%1,%2;" : "=l"(r) : "l"(a), "l"(b));
    return r;
}
__device__ __forceinline__ unsigned long long fma2(unsigned long long a, unsigned long long b,
                                                   unsigned long long c) {
    unsigned long long r;
    asm("fma.rn.f32x2 %0,%1,%2,%3;" : "=l"(r) : "l"(a), "l"(b), "l"(c));
    return r;
}

// distance pair: d01 for packed pixel pair (px01) vs packed negated pooled
#define DIST2(pa, pe, pf, n0, n1, n2, dout) do {                 \
    unsigned long long _dx = add2((pa), (n0));                   \
    unsigned long long _dy = add2((pe), (n1));                   \
    unsigned long long _dz = add2((pf), (n2));                   \
    (dout) = fma2(_dz, _dz, fma2(_dy, _dy, mul2(_dx, _dx)));     \
} while (0)

// ---------------------------------------------------------------------------
// Single fused kernel. CTA = (chunk, group, b): 4 pairs of image b over an
// 8192-pixel chunk. Two-pass threshold top-5 (see R8 comments), hot loops in
// packed f32x2 (per-lane IEEE identical to scalar).
// ---------------------------------------------------------------------------
__global__ void __launch_bounds__(THREADS, 3) cc_kernel(const float* __restrict__ preds,
                                                        const float* __restrict__ ref,
                                                        float* __restrict__ out) {
    const int chunk = blockIdx.x;
    const int group = blockIdx.y;
    const int b     = blockIdx.z;
    const int t = threadIdx.x, lane = t & 31, warp = t >> 5;

    // --- pooled colors for this CTA's 4 pairs (negated for add2-as-sub) ---
    __shared__ float s_p[GP][3];
    if (t < GP) {
        int l = group * GP + t;          // pair = b*64 + l
        int r = l * BS + b;              // flat row in pos_flat
        int sb = r >> 6, sl = r & 63;
        float x = preds[(sb * LEN + sl) * 8 + 0];
        float y = preds[(sb * LEN + sl) * 8 + 1];
        float cx = x * 256.0f - 0.5f;
        float cy = y * 256.0f - 0.5f;
        int ix = (int)rintf(cx);         // round-half-even == jnp.rint
        int iy = (int)rintf(cy);
        float v0 = 0.0f, v1 = 0.0f, v2 = 0.0f;
        if (ix >= 0 && ix < IMG && iy >= 0 && iy < IMG) {
            int off = iy * IMG + ix;
            v0 = ref[(b * 3 + 0) * NPIX + off];
            v1 = ref[(b * 3 + 1) * NPIX + off];
            v2 = ref[(b * 3 + 2) * NPIX + off];
        }
        s_p[t][0] = -v0; s_p[t][1] = -v1; s_p[t][2] = -v2;
    }
    __syncthreads();

    unsigned long long np[GP][3];        // packed (-p, -p)
#pragma unroll
    for (int j = 0; j < GP; j++)
#pragma unroll
        for (int c = 0; c < 3; c++) { float v = s_p[j][c]; np[j][c] = pk2(v, v); }

    // 128-bit loads land as two packed f32x2 (x,y) (z,w) — no pack movs
    const ulonglong2* __restrict__ r0 = (const ulonglong2*)(ref + (size_t)(b * 3 + 0) * NPIX);
    const ulonglong2* __restrict__ r1 = (const ulonglong2*)(ref + (size_t)(b * 3 + 1) * NPIX);
    const ulonglong2* __restrict__ r2 = (const ulonglong2*)(ref + (size_t)(b * 3 + 2) * NPIX);

    // ================= PASS 1: branchless per-thread min per pair ==========
    float mn[GP];
#pragma unroll
    for (int j = 0; j < GP; j++) mn[j] = 3e38f;

#pragma unroll 2
    for (int i = 0; i < ITERS; i++) {
        int gi = chunk * F4_PER_CHUNK + i * THREADS + t;   // coalesced 16B
        ulonglong2 a = r0[gi];
        ulonglong2 e = r1[gi];
        ulonglong2 f = r2[gi];
#pragma unroll
        for (int j = 0; j < GP; j++) {
            unsigned long long d01, d23;
            DIST2(a.x, e.x, f.x, np[j][0], np[j][1], np[j][2], d01);
            DIST2(a.y, e.y, f.y, np[j][0], np[j][1], np[j][2], d23);
            float d0, d1, d2, d3;
            upk2(d01, d0, d1);
            upk2(d23, d2, d3);
            mn[j] = fminf(mn[j], fminf(fminf(d0, d1), fminf(d2, d3)));
        }
    }

    // Per pair: warp 5th-smallest-with-removal, then min over warps.
    __shared__ float sT[GP][8];
#pragma unroll
    for (int j = 0; j < GP; j++) {
        float m = mn[j];
        float fifth = 3e38f;
#pragma unroll
        for (int k = 0; k < KSEL; k++) {
            float w = m;
#pragma unroll
            for (int off = 16; off; off >>= 1) w = fminf(w, __shfl_xor_sync(0xffffffffu, w, off));
            if (m == w) m = 3e38f;       // remove (ties all removed -> T only grows: safe)
            fifth = w;
        }
        if (lane == 0) sT[j][warp] = fifth;
    }
    __syncthreads();

    float Tj[GP];
#pragma unroll
    for (int j = 0; j < GP; j++) {
        float x = sT[j][0];
#pragma unroll
        for (int w = 1; w < 8; w++) x = fminf(x, sT[j][w]);
        Tj[j] = x;                        // >= chunk's 5th-smallest distance
    }

    // ================= PASS 2: collect candidates d <= T ===================
    __shared__ unsigned long long cand[GP][CAP];
    __shared__ int cnt[GP];
    if (t < GP) cnt[t] = 0;
    __syncthreads();

#pragma unroll 2
    for (int i = 0; i < ITERS; i++) {
        int gi = chunk * F4_PER_CHUNK + i * THREADS + t;
        ulonglong2 a = r0[gi];
        ulonglong2 e = r1[gi];
        ulonglong2 f = r2[gi];
        int base = gi * 4;
#pragma unroll
        for (int j = 0; j < GP; j++) {
            unsigned long long d01, d23;
            DIST2(a.x, e.x, f.x, np[j][0], np[j][1], np[j][2], d01);
            DIST2(a.y, e.y, f.y, np[j][0], np[j][1], np[j][2], d23);
            float d0, d1, d2, d3;
            upk2(d01, d0, d1);
            upk2(d23, d2, d3);
            float m = fminf(fminf(d0, d1), fminf(d2, d3));
            float T = Tj[j];
            if (m <= T) {                 // rare path
                if (d0 <= T) { int s = atomicAdd(&cnt[j], 1);
                    if (s < CAP) cand[j][s] = ((unsigned long long)__float_as_uint(d0) << 32) | (unsigned int)(base + 0); }
                if (d1 <= T) { int s = atomicAdd(&cnt[j], 1);
                    if (s < CAP) cand[j][s] = ((unsigned long long)__float_as_uint(d1) << 32) | (unsigned int)(base + 1); }
                if (d2 <= T) { int s = atomicAdd(&cnt[j], 1);
                    if (s < CAP) cand[j][s] = ((unsigned long long)__float_as_uint(d2) << 32) | (unsigned int)(base + 2); }
                if (d3 <= T) { int s = atomicAdd(&cnt[j], 1);
                    if (s < CAP) cand[j][s] = ((unsigned long long)__float_as_uint(d3) << 32) | (unsigned int)(base + 3); }
            }
        }
    }
    __syncthreads();

    // Warps 0..3: warp j selects exact top-5 of pair j's candidates.
    if (warp < GP) {
        int j = warp;
        int n = cnt[j] < CAP ? cnt[j] : CAP;   // n >= 5 guaranteed by T
        unsigned long long v0 = (lane      < n) ? cand[j][lane]      : 0xFFFFFFFFFFFFFFFFull;
        unsigned long long v1 = (lane + 32 < n) ? cand[j][lane + 32] : 0xFFFFFFFFFFFFFFFFull;
        unsigned long long v2 = (lane + 64 < n) ? cand[j][lane + 64] : 0xFFFFFFFFFFFFFFFFull;
        int pair = b * LEN + group * GP + j;
#pragma unroll
        for (int k = 0; k < KSEL; k++) {
            unsigned long long m = v0 < v1 ? v0 : v1;
            if (v2 < m) m = v2;
#pragma unroll
            for (int off = 16; off; off >>= 1) {
                unsigned long long o = __shfl_xor_sync(0xffffffffu, m, off);
                if (o < m) m = o;
            }
            if (lane == 0) g_part[pair][chunk][k] = m;
            if (v0 == m) v0 = 0xFFFFFFFFFFFFFFFFull;
            if (v1 == m) v1 = 0xFFFFFFFFFFFFFFFFull;
            if (v2 == m) v2 = 0xFFFFFFFFFFFFFFFFull;
        }
    }
    __threadfence();                      // release g_part before counter
    __syncthreads();

    // ================= last CTA: merge + loss ==============================
    __shared__ int isLast;
    if (t == 0) {
        int prev = atomicAdd(&g_done, 1);
        isLast = (prev == NCTAS - 1);
    }
    __syncthreads();
    if (!isLast) return;
    if (t == 0) g_done = 0;               // reset for next graph replay
    __threadfence();

    __shared__ unsigned int s_idx[NPAIR][KSEL];
#pragma unroll
    for (int rep = 0; rep < 2; rep++) {
        int p = t + rep * 256;
        unsigned long long b0 = ~0ull, b1 = ~0ull, b2 = ~0ull, b3 = ~0ull, b4 = ~0ull;
#pragma unroll
        for (int c = 0; c < CHUNKS; c++) {
#pragma unroll
            for (int k = 0; k < KSEL; k++) {
                unsigned long long v = g_part[p][c][k];
                if (v < b4) {
                    if (v < b3) { b4 = b3;
                        if (v < b2) { b3 = b2;
                            if (v < b1) { b2 = b1;
                                if (v < b0) { b1 = b0; b0 = v; } else b1 = v;
                            } else b2 = v;
                        } else b3 = v;
                    } else b4 = v;
                }
            }
        }
        s_idx[p][0] = (unsigned int)b0;
        s_idx[p][1] = (unsigned int)b1;
        s_idx[p][2] = (unsigned int)b2;
        s_idx[p][3] = (unsigned int)b3;
        s_idx[p][4] = (unsigned int)b4;
    }
    __syncthreads();

    float acc = 0.0f;
#pragma unroll
    for (int rep = 0; rep < 2; rep++) {
        int p = t + rep * 256;
        int pb = p >> 6, pl = p & 63;
        if (pl >= 1) {
            float px = preds[(pb * LEN + pl) * 8 + 0];
            float py = preds[(pb * LEN + pl) * 8 + 1];
            int src = pb * LEN + (pl - 1);        // tgt_down[b,l] = tgt[b,l-1]
            float bestD = 3e38f, bx = 0.0f, by = 0.0f;
#pragma unroll
            for (int k = 0; k < KSEL; k++) {
                unsigned int idx = s_idx[src][k];
                float tx = (float)(idx & 255u) * (1.0f / 256.0f);
                float ty = (float)(idx >> 8)   * (1.0f / 256.0f);
                float ddx = px - tx, ddy = py - ty;
                float dd = ddx * ddx + ddy * ddy;
                if (dd < bestD) { bestD = dd; bx = tx; by = ty; }  // first min wins
            }
            float ex = px - bx, ey = py - by;
            acc += ex * ex + ey * ey;
        }
    }

    __shared__ float s[256];
    s[t] = acc;
    __syncthreads();
    for (int st = 128; st; st >>= 1) {
        if (t < st) s[t] += s[t + st];
        __syncthreads();
    }
    if (t == 0) out[0] = s[0] / (float)(BS * (LEN - 1));
}

// ---------------------------------------------------------------------------
extern "C" void kernel_launch(void* const* d_in, const int* in_sizes, int n_in,
                              void* d_out, int out_size) {
    const float* preds = (const float*)d_in[0];   // (8, 64, 8) float32
    const float* ref   = (const float*)d_in[1];   // (8, 3, 256, 256) float32
    float* out = (float*)d_out;

    dim3 grid(CHUNKS, GROUPS, BS);
    cc_kernel<<<grid, THREADS>>>(preds, ref, out);
}